// round 5
// baseline (speedup 1.0000x reference)
#include <cuda_runtime.h>
#include <cuda_bf16.h>
#include <math.h>
#include <stdint.h>

// ---------------- problem constants ----------------
#define NT   16384      // B*S tokens
#define H    2048
#define E    256
#define THID 512
#define T    128
#define NREG 64         // NUM_REGISTERED_TOOLS

// ---------------- scratch (device globals: no allocs allowed) ----------------
__device__ float g_hid[(long)NT * THID];      // 32 MB: sel-h1, then pg-h1 / ri-h1 (compact)
__device__ float g_toolres[(long)NT * H];     // 128 MB
__device__ float g_logits[(long)NT * T];      // 8 MB
__device__ float g_gate[NT];
__device__ int   g_active[NT];
__device__ int   g_tool[NT];
__device__ int   g_count[1];

// ---------------- tiny kernels ----------------
__global__ void init_kernel() { g_count[0] = 0; }

// copy hidden -> out AND compute gate dot product (single pass over hidden)
__global__ __launch_bounds__(256) void copy_gate_kernel(
    const float* __restrict__ src, const float* __restrict__ gw,
    float* __restrict__ dst)
{
    __shared__ float red[8];
    int t = blockIdx.x, tid = threadIdx.x;
    long base = (long)t * H + tid * 8;
    float4 a = *(const float4*)(src + base);
    float4 b = *(const float4*)(src + base + 4);
    *(float4*)(dst + base)     = a;
    *(float4*)(dst + base + 4) = b;
    float4 w0 = *(const float4*)(gw + tid * 8);
    float4 w1 = *(const float4*)(gw + tid * 8 + 4);
    float acc = a.x*w0.x + a.y*w0.y + a.z*w0.z + a.w*w0.w
              + b.x*w1.x + b.y*w1.y + b.z*w1.z + b.w*w1.w;
#pragma unroll
    for (int off = 16; off >= 1; off >>= 1)
        acc += __shfl_xor_sync(0xffffffffu, acc, off);
    if ((tid & 31) == 0) red[tid >> 5] = acc;
    __syncthreads();
    if (tid == 0) {
        float s = 0.f;
#pragma unroll
        for (int i = 0; i < 8; i++) s += red[i];
        g_gate[t] = s;
    }
}

// top-k/softmax/gate/compaction: one warp per token, reads g_logits
__global__ __launch_bounds__(256) void topk_kernel(
    const float* __restrict__ gate_b,
    float* __restrict__ out_probs, float* __restrict__ out_should)
{
    int t = blockIdx.x * 8 + (threadIdx.x >> 5);
    int l = threadIdx.x & 31;
    float4 v = *(const float4*)(g_logits + (long)t * T + l * 4);
    float lg[4] = {v.x, v.y, v.z, v.w};
    int topi[3];
    unsigned mask = 0;
    float mx = 0.f;
#pragma unroll
    for (int r = 0; r < 3; r++) {
        float bv = -3.4e38f; int bi = 1 << 30;
#pragma unroll
        for (int j = 0; j < 4; j++) {
            if (!((mask >> j) & 1)) {
                int c = l * 4 + j;
                if (lg[j] > bv || (lg[j] == bv && c < bi)) { bv = lg[j]; bi = c; }
            }
        }
#pragma unroll
        for (int off = 16; off >= 1; off >>= 1) {
            float ov = __shfl_xor_sync(0xffffffffu, bv, off);
            int   oi = __shfl_xor_sync(0xffffffffu, bi, off);
            if (ov > bv || (ov == bv && oi < bi)) { bv = ov; bi = oi; }
        }
        if (r == 0) mx = bv;
        topi[r] = bi;
        if ((bi >> 2) == l) mask |= 1u << (bi & 3);
    }
    float e[4], s = 0.f;
#pragma unroll
    for (int j = 0; j < 4; j++) { e[j] = expf(lg[j] - mx); s += e[j]; }
#pragma unroll
    for (int off = 16; off >= 1; off >>= 1)
        s += __shfl_xor_sync(0xffffffffu, s, off);
    if (out_probs)
        *(float4*)(out_probs + (long)t * T + l * 4) = make_float4(e[0]/s, e[1]/s, e[2]/s, e[3]/s);
    if (l == 0) {
        bool should = (g_gate[t] + gate_b[0]) > 0.f;
        if (out_should) out_should[t] = should ? 1.0f : 0.0f;
        int last = -1, tool = 0;
#pragma unroll
        for (int k = 0; k < 3; k++)
            if (should && topi[k] < NREG) { last = k; tool = topi[k]; }
        if (last >= 0) {
            int pos = atomicAdd(g_count, 1);
            g_active[pos] = t;
            g_tool[pos]   = tool;
        }
    }
}

// ---------------- fp32 FFMA GEMM (selector path: exactness protects top-k) ----------------
// asel: 0 A=Aext, 1 A=g_hid.   dsel: 0 g_hid, 3 g_logits
__global__ __launch_bounds__(256, 2) void gemm_kernel(
    int asel, int dsel, int do_relu,
    const float* __restrict__ Aext, int lda,
    const float* __restrict__ W, int ldw,    // [K, N] row-major
    const float* __restrict__ bias,
    int ldc, int K)
{
    __shared__ float As[16][132];
    __shared__ float Ws[16][128];

    int m0 = blockIdx.y * 128;
    int n0 = blockIdx.x * 128;
    int tid = threadIdx.x;
    const float* A0 = asel ? g_hid : Aext;

    int ra = tid >> 2;
    int kq = (tid & 3) * 4;
    const float* baseP[2];
#pragma unroll
    for (int i = 0; i < 2; i++)
        baseP[i] = A0 + (long)(m0 + ra + i * 64) * lda;

    int wk = tid >> 5;
    int wn = (tid & 31) * 4;

    float acc[8][8];
#pragma unroll
    for (int i = 0; i < 8; i++)
#pragma unroll
        for (int j = 0; j < 8; j++) acc[i][j] = 0.f;

    int tx = tid & 15, ty = tid >> 4;

    for (int k0 = 0; k0 < K; k0 += 16) {
#pragma unroll
        for (int i = 0; i < 2; i++) {
            float4 v = *(const float4*)(baseP[i] + k0 + kq);
            int m = ra + i * 64;
            As[kq + 0][m] = v.x; As[kq + 1][m] = v.y;
            As[kq + 2][m] = v.z; As[kq + 3][m] = v.w;
        }
#pragma unroll
        for (int i = 0; i < 2; i++) {
            int k = wk + i * 8;
            float4 v = *(const float4*)(W + (long)(k0 + k) * ldw + n0 + wn);
            *(float4*)&Ws[k][wn] = v;
        }
        __syncthreads();
#pragma unroll
        for (int kk = 0; kk < 16; kk++) {
            float a[8], b[8];
            *(float4*)(a)     = *(const float4*)&As[kk][ty * 8];
            *(float4*)(a + 4) = *(const float4*)&As[kk][ty * 8 + 4];
            *(float4*)(b)     = *(const float4*)&Ws[kk][tx * 8];
            *(float4*)(b + 4) = *(const float4*)&Ws[kk][tx * 8 + 4];
#pragma unroll
            for (int i = 0; i < 8; i++)
#pragma unroll
                for (int j = 0; j < 8; j++)
                    acc[i][j] = fmaf(a[i], b[j], acc[i][j]);
        }
        __syncthreads();
    }

    float* Cbase = (dsel == 0) ? g_hid : g_logits;
#pragma unroll
    for (int i = 0; i < 8; i++) {
        long row = m0 + ty * 8 + i;
        float* cp = Cbase + row * ldc + n0 + tx * 8;
#pragma unroll
        for (int jj = 0; jj < 8; jj += 4) {
            float4 v;
            v.x = acc[i][jj + 0] + bias[n0 + tx * 8 + jj + 0];
            v.y = acc[i][jj + 1] + bias[n0 + tx * 8 + jj + 1];
            v.z = acc[i][jj + 2] + bias[n0 + tx * 8 + jj + 2];
            v.w = acc[i][jj + 3] + bias[n0 + tx * 8 + jj + 3];
            if (do_relu) {
                v.x = fmaxf(v.x, 0.f); v.y = fmaxf(v.y, 0.f);
                v.z = fmaxf(v.z, 0.f); v.w = fmaxf(v.w, 0.f);
            }
            *(float4*)(cp + jj) = v;
        }
    }
}

// ---------------- mma.sync bf16 3-pass GEMM (pg/ri path, value-only precision) ----------------
// CTA tile M=64, N=128, Kstage=32, double-buffered smem.
// Split: x = hi + lo (bf16); D += Ahi*Whi + Alo*Whi + Ahi*Wlo  (error ~2^-18).
// mode: 0 direct rows, 1 gather token + concat emb, 2 gather token + concat toolres
// asel: 0 A=Aext, 1 A=g_hid.   dsel: 0 g_hid, 1 g_toolres, 2 Cext(+scatter)

#define A_STRIDE 72                     // bytes per A smem row (32 bf16 + pad)
#define W_STRIDE 68                     // bytes per W smem row (32 bf16 + pad)
#define OFF_A_HI 0
#define OFF_A_LO (64 * A_STRIDE)                    // 4608
#define OFF_W_HI (2 * 64 * A_STRIDE)                // 9216
#define OFF_W_LO (OFF_W_HI + 128 * W_STRIDE)        // 17920
#define BUF_SZ   (OFF_W_LO + 128 * W_STRIDE)        // 26624
#define MMA_SMEM (2 * BUF_SZ)                       // 53248

// W smem bank swizzle: kp (= k>>1) XORed with bits 5..6 of n (store-conflict-free)
__device__ __forceinline__ int w_off(int n, int kp) {
    return n * W_STRIDE + 4 * (kp ^ ((n >> 5) & 3));
}

__device__ __forceinline__ void mma16816(float* c, const uint32_t* a, const uint32_t* b) {
    asm volatile(
        "mma.sync.aligned.m16n8k16.row.col.f32.bf16.bf16.f32 "
        "{%0,%1,%2,%3}, {%4,%5,%6,%7}, {%8,%9}, {%0,%1,%2,%3};\n"
        : "+f"(c[0]), "+f"(c[1]), "+f"(c[2]), "+f"(c[3])
        : "r"(a[0]), "r"(a[1]), "r"(a[2]), "r"(a[3]), "r"(b[0]), "r"(b[1]));
}

__device__ __forceinline__ uint32_t pack_hi2(float x, float y) {
    __nv_bfloat16 hx = __float2bfloat16(x), hy = __float2bfloat16(y);
    return (uint32_t)__bfloat16_as_ushort(hx) | ((uint32_t)__bfloat16_as_ushort(hy) << 16);
}
__device__ __forceinline__ uint32_t pack_lo2(float x, float y) {
    __nv_bfloat16 hx = __float2bfloat16(x), hy = __float2bfloat16(y);
    __nv_bfloat16 lx = __float2bfloat16(x - __bfloat162float(hx));
    __nv_bfloat16 ly = __float2bfloat16(y - __bfloat162float(hy));
    return (uint32_t)__bfloat16_as_ushort(lx) | ((uint32_t)__bfloat16_as_ushort(ly) << 16);
}

__global__ __launch_bounds__(256) void mma_gemm_kernel(
    int mode, int asel, int dsel, int do_relu, int do_scatter,
    const float* __restrict__ Aext, int lda,
    const float* __restrict__ Bsec, int splitK,
    const float* __restrict__ W, int ldw,
    const float* __restrict__ bias,
    float* __restrict__ Cext, int ldc, int K)
{
    extern __shared__ __align__(16) char smem[];
    int Meff = g_count[0];
    int m0 = blockIdx.y * 64;
    if (m0 >= Meff) return;
    int n0 = blockIdx.x * 128;
    int tid = threadIdx.x;
    int wid = tid >> 5;
    int lane = tid & 31;
    int wm = wid & 1;       // m half (32 rows)
    int wn = wid >> 1;      // n quarter (32 cols)

    // ---- A loader mapping: 4 threads per row, 8 k's each ----
    int arow = tid >> 2;
    int ak   = (tid & 3) * 8;
    const float* A0 = asel ? g_hid : Aext;
    const float* prim;
    const float* sec;
    {
        int rg = m0 + arow;
        if (mode == 0) {
            prim = A0 + (long)rg * lda;
            sec  = prim;
        } else {
            int rr  = (rg < Meff) ? rg : (Meff - 1);
            int tok = g_active[rr];
            prim = Aext + (long)tok * lda;
            sec  = (mode == 1) ? (Bsec + (long)g_tool[rr] * E)
                               : (g_toolres + (long)rr * H);
        }
    }
    // ---- W loader mapping: 32 threads across n (coalesced), 8 k rows base ----
    int wn4 = (tid & 31) * 4;
    int wkb = tid >> 5;

    float4 aq0, aq1;
    float4 wq[4];
    int S = K / 32;

    float acc[2][4][4];
#pragma unroll
    for (int i = 0; i < 2; i++)
#pragma unroll
        for (int j = 0; j < 4; j++)
#pragma unroll
            for (int q = 0; q < 4; q++) acc[i][j][q] = 0.f;

    // ---- prologue: load + store stage 0 ----
    {
        int k0 = ak;
        const float* src = (k0 < splitK) ? (prim + k0) : (sec + (k0 - splitK));
        aq0 = *(const float4*)(src);
        aq1 = *(const float4*)(src + 4);
#pragma unroll
        for (int i = 0; i < 4; i++)
            wq[i] = *(const float4*)(W + (long)(wkb + 8 * i) * ldw + n0 + wn4);
    }
    {
        char* bp = smem;
        int ab = arow * A_STRIDE + 2 * ak;
        *(uint32_t*)(bp + OFF_A_HI + ab)      = pack_hi2(aq0.x, aq0.y);
        *(uint32_t*)(bp + OFF_A_HI + ab + 4)  = pack_hi2(aq0.z, aq0.w);
        *(uint32_t*)(bp + OFF_A_HI + ab + 8)  = pack_hi2(aq1.x, aq1.y);
        *(uint32_t*)(bp + OFF_A_HI + ab + 12) = pack_hi2(aq1.z, aq1.w);
        *(uint32_t*)(bp + OFF_A_LO + ab)      = pack_lo2(aq0.x, aq0.y);
        *(uint32_t*)(bp + OFF_A_LO + ab + 4)  = pack_lo2(aq0.z, aq0.w);
        *(uint32_t*)(bp + OFF_A_LO + ab + 8)  = pack_lo2(aq1.x, aq1.y);
        *(uint32_t*)(bp + OFF_A_LO + ab + 12) = pack_lo2(aq1.z, aq1.w);
        const float* wv = (const float*)wq;
#pragma unroll
        for (int i = 0; i < 4; i++) {
            int k = wkb + 8 * i;
#pragma unroll
            for (int j = 0; j < 4; j++) {
                float x = wv[i * 4 + j];
                int n = wn4 + j;
                int off = w_off(n, k >> 1) + (k & 1) * 2;
                __nv_bfloat16 hx = __float2bfloat16(x);
                __nv_bfloat16 lx = __float2bfloat16(x - __bfloat162float(hx));
                *(uint16_t*)(bp + OFF_W_HI + off) = __bfloat16_as_ushort(hx);
                *(uint16_t*)(bp + OFF_W_LO + off) = __bfloat16_as_ushort(lx);
            }
        }
    }
    __syncthreads();

    int g  = lane >> 2;
    int j2 = lane & 3;

    for (int s = 0; s < S; s++) {
        // prefetch next stage into registers
        if (s + 1 < S) {
            int k0 = (s + 1) * 32 + ak;
            const float* src = (k0 < splitK) ? (prim + k0) : (sec + (k0 - splitK));
            aq0 = *(const float4*)(src);
            aq1 = *(const float4*)(src + 4);
#pragma unroll
            for (int i = 0; i < 4; i++)
                wq[i] = *(const float4*)(W + (long)((s + 1) * 32 + wkb + 8 * i) * ldw + n0 + wn4);
        }
        // compute current stage
        {
            char* bp = smem + (s & 1) * BUF_SZ;
            const char* Ah = bp + OFF_A_HI;
            const char* Al = bp + OFF_A_LO;
            const char* Wh = bp + OFF_W_HI;
            const char* Wl = bp + OFF_W_LO;
#pragma unroll
            for (int ks = 0; ks < 2; ks++) {
                int kk = ks * 16 + j2 * 2;
                uint32_t ahi[2][4], alo[2][4];
#pragma unroll
                for (int mi = 0; mi < 2; mi++) {
                    int row = wm * 32 + mi * 16 + g;
                    int b0 = row * A_STRIDE + 2 * kk;
                    ahi[mi][0] = *(const uint32_t*)(Ah + b0);
                    ahi[mi][1] = *(const uint32_t*)(Ah + b0 + 8 * A_STRIDE);
                    ahi[mi][2] = *(const uint32_t*)(Ah + b0 + 16);
                    ahi[mi][3] = *(const uint32_t*)(Ah + b0 + 8 * A_STRIDE + 16);
                    alo[mi][0] = *(const uint32_t*)(Al + b0);
                    alo[mi][1] = *(const uint32_t*)(Al + b0 + 8 * A_STRIDE);
                    alo[mi][2] = *(const uint32_t*)(Al + b0 + 16);
                    alo[mi][3] = *(const uint32_t*)(Al + b0 + 8 * A_STRIDE + 16);
                }
                uint32_t whi[4][2], wlo[4][2];
#pragma unroll
                for (int nf = 0; nf < 4; nf++) {
                    int n = wn * 32 + nf * 8 + g;
                    int o0 = w_off(n, kk >> 1);
                    int o1 = w_off(n, (kk + 8) >> 1);
                    whi[nf][0] = *(const uint32_t*)(Wh + o0);
                    whi[nf][1] = *(const uint32_t*)(Wh + o1);
                    wlo[nf][0] = *(const uint32_t*)(Wl + o0);
                    wlo[nf][1] = *(const uint32_t*)(Wl + o1);
                }
#pragma unroll
                for (int mi = 0; mi < 2; mi++)
#pragma unroll
                    for (int nf = 0; nf < 4; nf++) {
                        mma16816(acc[mi][nf], ahi[mi], whi[nf]);
                        mma16816(acc[mi][nf], alo[mi], whi[nf]);
                        mma16816(acc[mi][nf], ahi[mi], wlo[nf]);
                    }
            }
        }
        __syncthreads();
        // store next stage
        if (s + 1 < S) {
            char* bp = smem + ((s + 1) & 1) * BUF_SZ;
            int ab = arow * A_STRIDE + 2 * ak;
            *(uint32_t*)(bp + OFF_A_HI + ab)      = pack_hi2(aq0.x, aq0.y);
            *(uint32_t*)(bp + OFF_A_HI + ab + 4)  = pack_hi2(aq0.z, aq0.w);
            *(uint32_t*)(bp + OFF_A_HI + ab + 8)  = pack_hi2(aq1.x, aq1.y);
            *(uint32_t*)(bp + OFF_A_HI + ab + 12) = pack_hi2(aq1.z, aq1.w);
            *(uint32_t*)(bp + OFF_A_LO + ab)      = pack_lo2(aq0.x, aq0.y);
            *(uint32_t*)(bp + OFF_A_LO + ab + 4)  = pack_lo2(aq0.z, aq0.w);
            *(uint32_t*)(bp + OFF_A_LO + ab + 8)  = pack_lo2(aq1.x, aq1.y);
            *(uint32_t*)(bp + OFF_A_LO + ab + 12) = pack_lo2(aq1.z, aq1.w);
            const float* wv = (const float*)wq;
#pragma unroll
            for (int i = 0; i < 4; i++) {
                int k = wkb + 8 * i;
#pragma unroll
                for (int j = 0; j < 4; j++) {
                    float x = wv[i * 4 + j];
                    int n = wn4 + j;
                    int off = w_off(n, k >> 1) + (k & 1) * 2;
                    __nv_bfloat16 hx = __float2bfloat16(x);
                    __nv_bfloat16 lx = __float2bfloat16(x - __bfloat162float(hx));
                    *(uint16_t*)(bp + OFF_W_HI + off) = __bfloat16_as_ushort(hx);
                    *(uint16_t*)(bp + OFF_W_LO + off) = __bfloat16_as_ushort(lx);
                }
            }
            __syncthreads();
        }
    }

    // ---- epilogue ----
    float* Cb = (dsel == 0) ? g_hid : ((dsel == 1) ? g_toolres : Cext);
#pragma unroll
    for (int mi = 0; mi < 2; mi++) {
#pragma unroll
        for (int h = 0; h < 2; h++) {
            int m = m0 + wm * 32 + mi * 16 + g + 8 * h;
            bool ok = !(do_scatter && m >= Meff);
            if (!ok) continue;
            long orow = do_scatter ? (long)g_active[m] : (long)m;
            float* rp = Cb + orow * ldc;
#pragma unroll
            for (int nf = 0; nf < 4; nf++) {
                int n = n0 + wn * 32 + nf * 8 + j2 * 2;
                float2 v;
                v.x = acc[mi][nf][h * 2 + 0] + bias[n];
                v.y = acc[mi][nf][h * 2 + 1] + bias[n + 1];
                if (do_relu) { v.x = fmaxf(v.x, 0.f); v.y = fmaxf(v.y, 0.f); }
                *(float2*)(rp + n) = v;
            }
        }
    }
}

// ---------------- launch ----------------
extern "C" void kernel_launch(void* const* d_in, const int* in_sizes, int n_in,
                              void* d_out, int out_size)
{
    const float* hidden = (const float*)d_in[0];
    const float* emb    = (const float*)d_in[1];
    const float* gate_w = (const float*)d_in[2];
    const float* gate_b = (const float*)d_in[3];
    const float* sel_w1 = (const float*)d_in[4];
    const float* sel_b1 = (const float*)d_in[5];
    const float* sel_w2 = (const float*)d_in[6];
    const float* sel_b2 = (const float*)d_in[7];
    const float* pg_w1  = (const float*)d_in[8];
    const float* pg_b1  = (const float*)d_in[9];
    const float* pg_w2  = (const float*)d_in[10];
    const float* pg_b2  = (const float*)d_in[11];
    const float* ri_w1  = (const float*)d_in[12];
    const float* ri_b1  = (const float*)d_in[13];
    const float* ri_w2  = (const float*)d_in[14];
    const float* ri_b2  = (const float*)d_in[15];

    float* out        = (float*)d_out;
    float* out_enh    = out;
    float* out_probs  = ((long)out_size >= (long)NT * (H + T))     ? out + (long)NT * H       : nullptr;
    float* out_should = ((long)out_size >= (long)NT * (H + T + 1)) ? out + (long)NT * (H + T) : nullptr;

    cudaFuncSetAttribute(mma_gemm_kernel, cudaFuncAttributeMaxDynamicSharedMemorySize, MMA_SMEM);

    // 0) reset compaction counter
    init_kernel<<<1, 1>>>();

    // 1) enhanced = hidden (default) + gate dot product, fused
    copy_gate_kernel<<<NT, 256>>>(hidden, gate_w, out_enh);

    // 2) sel1 (fp32 exact): h1 = relu(hidden @ sel_w1 + b1) -> g_hid [NT,512]
    gemm_kernel<<<dim3(THID / 128, NT / 128), 256>>>(
        0, 0, 1, hidden, H, sel_w1, THID, sel_b1, THID, H);

    // 3) sel2 (fp32 exact): logits = g_hid @ sel_w2 + b2 -> g_logits [NT,128]
    gemm_kernel<<<dim3(T / 128, NT / 128), 256>>>(
        1, 3, 0, nullptr, THID, sel_w2, T, sel_b2, T, THID);

    // 4) top-3 + softmax + gate + compaction
    topk_kernel<<<NT / 8, 256>>>(gate_b, out_probs, out_should);

    // 5) pg1 (mma): relu(concat(h, emb[tool]) @ pg_w1 + b1) -> g_hid (compact)
    mma_gemm_kernel<<<dim3(THID / 128, NT / 64), 256, MMA_SMEM>>>(
        1, 0, 0, 1, 0, hidden, H, emb, H, pg_w1, THID, pg_b1, nullptr, THID, H + E);

    // 6) pg2 (mma): tool_result = g_hid @ pg_w2 + b2 -> g_toolres
    mma_gemm_kernel<<<dim3(H / 128, NT / 64), 256, MMA_SMEM>>>(
        0, 1, 1, 0, 0, nullptr, THID, nullptr, THID, pg_w2, H, pg_b2, nullptr, H, THID);

    // 7) ri1 (mma): relu(concat(h, tool_result) @ ri_w1 + b1) -> g_hid
    mma_gemm_kernel<<<dim3(THID / 128, NT / 64), 256, MMA_SMEM>>>(
        2, 0, 0, 1, 0, hidden, H, nullptr, H, ri_w1, THID, ri_b1, nullptr, THID, 2 * H);

    // 8) ri2 (mma): integrated = g_hid @ ri_w2 + b2, scatter into enhanced
    mma_gemm_kernel<<<dim3(H / 128, NT / 64), 256, MMA_SMEM>>>(
        0, 1, 2, 0, 1, nullptr, THID, nullptr, THID, ri_w2, H, ri_b2, out_enh, H, THID);
}

// round 8
// speedup vs baseline: 1.1066x; 1.1066x over previous
#include <cuda_runtime.h>
#include <cuda_bf16.h>
#include <math.h>
#include <stdint.h>

// ---------------- problem constants ----------------
#define NT   16384      // B*S tokens
#define H    2048
#define E    256
#define THID 512
#define T    128
#define NREG 64

typedef __nv_bfloat16 bf16;

// ---------------- scratch (device globals) ----------------
__device__ float g_hid[(long)NT * THID];          // sel h1 (fp32, selector path)
__device__ uint4 g_gh[2][(long)NT * H / 8];       // hidden bf16 planes (hi, lo)
__device__ uint4 g_hp[2][(long)NT * THID / 8];    // pg-h1 planes; reused for ri-h1
__device__ uint4 g_tr[2][(long)NT * H / 8];       // tool_result planes
__device__ uint4 g_eb[2][T * E / 8];              // emb planes
__device__ uint4 g_pw1t[2][THID * (H + E) / 8];   // pg_w1^T planes [N][K]
__device__ uint4 g_pw2t[2][H * THID / 8];
__device__ uint4 g_rw1t[2][THID * 2 * H / 8];
__device__ uint4 g_rw2t[2][H * THID / 8];

__device__ float g_logits[(long)NT * T];
__device__ float g_gate[NT];
__device__ int   g_active[NT];
__device__ int   g_tool[NT];
__device__ int   g_count[1];

// ---------------- ptx helpers ----------------
__device__ __forceinline__ uint32_t smem_u32(const void* p) {
    uint32_t a;
    asm("{ .reg .u64 tmp; cvta.to.shared.u64 tmp, %1; cvt.u32.u64 %0, tmp; }"
        : "=r"(a) : "l"(p));
    return a;
}
__device__ __forceinline__ void cp16(uint32_t dst, const void* src) {
    asm volatile("cp.async.ca.shared.global [%0], [%1], 16;" :: "r"(dst), "l"(src));
}
__device__ __forceinline__ void cp_commit() { asm volatile("cp.async.commit_group;" ::: "memory"); }
__device__ __forceinline__ void cp_wait0()  { asm volatile("cp.async.wait_group 0;" ::: "memory"); }
__device__ __forceinline__ void cp_wait1()  { asm volatile("cp.async.wait_group 1;" ::: "memory"); }

// ---------------- tiny kernels ----------------
__global__ void init_kernel() { g_count[0] = 0; }

__global__ __launch_bounds__(256) void copy_gate_kernel(
    const float* __restrict__ src, const float* __restrict__ gw,
    float* __restrict__ dst)
{
    __shared__ float red[8];
    int t = blockIdx.x, tid = threadIdx.x;
    long base = (long)t * H + tid * 8;
    float4 a = *(const float4*)(src + base);
    float4 b = *(const float4*)(src + base + 4);
    *(float4*)(dst + base)     = a;
    *(float4*)(dst + base + 4) = b;
    float4 w0 = *(const float4*)(gw + tid * 8);
    float4 w1 = *(const float4*)(gw + tid * 8 + 4);
    float acc = a.x*w0.x + a.y*w0.y + a.z*w0.z + a.w*w0.w
              + b.x*w1.x + b.y*w1.y + b.z*w1.z + b.w*w1.w;
#pragma unroll
    for (int off = 16; off >= 1; off >>= 1)
        acc += __shfl_xor_sync(0xffffffffu, acc, off);
    if ((tid & 31) == 0) red[tid >> 5] = acc;
    __syncthreads();
    if (tid == 0) {
        float s = 0.f;
#pragma unroll
        for (int i = 0; i < 8; i++) s += red[i];
        g_gate[t] = s;
    }
}

__global__ __launch_bounds__(256) void topk_kernel(
    const float* __restrict__ gate_b,
    float* __restrict__ out_probs, float* __restrict__ out_should)
{
    int t = blockIdx.x * 8 + (threadIdx.x >> 5);
    int l = threadIdx.x & 31;
    float4 v = *(const float4*)(g_logits + (long)t * T + l * 4);
    float lg[4] = {v.x, v.y, v.z, v.w};
    int topi[3];
    unsigned mask = 0;
    float mx = 0.f;
#pragma unroll
    for (int r = 0; r < 3; r++) {
        float bv = -3.4e38f; int bi = 1 << 30;
#pragma unroll
        for (int j = 0; j < 4; j++) {
            if (!((mask >> j) & 1)) {
                int c = l * 4 + j;
                if (lg[j] > bv || (lg[j] == bv && c < bi)) { bv = lg[j]; bi = c; }
            }
        }
#pragma unroll
        for (int off = 16; off >= 1; off >>= 1) {
            float ov = __shfl_xor_sync(0xffffffffu, bv, off);
            int   oi = __shfl_xor_sync(0xffffffffu, bi, off);
            if (ov > bv || (ov == bv && oi < bi)) { bv = ov; bi = oi; }
        }
        if (r == 0) mx = bv;
        topi[r] = bi;
        if ((bi >> 2) == l) mask |= 1u << (bi & 3);
    }
    float e[4], s = 0.f;
#pragma unroll
    for (int j = 0; j < 4; j++) { e[j] = expf(lg[j] - mx); s += e[j]; }
#pragma unroll
    for (int off = 16; off >= 1; off >>= 1)
        s += __shfl_xor_sync(0xffffffffu, s, off);
    if (out_probs)
        *(float4*)(out_probs + (long)t * T + l * 4) = make_float4(e[0]/s, e[1]/s, e[2]/s, e[3]/s);
    if (l == 0) {
        bool should = (g_gate[t] + gate_b[0]) > 0.f;
        if (out_should) out_should[t] = should ? 1.0f : 0.0f;
        int last = -1, tool = 0;
#pragma unroll
        for (int k = 0; k < 3; k++)
            if (should && topi[k] < NREG) { last = k; tool = topi[k]; }
        if (last >= 0) {
            int pos = atomicAdd(g_count, 1);
            g_active[pos] = t;
            g_tool[pos]   = tool;
        }
    }
}

// ---------------- split helpers ----------------
__device__ __forceinline__ void split2f(float x, bf16& h, bf16& l) {
    h = __float2bfloat16(x);
    l = __float2bfloat16(x - __bfloat162float(h));
}
__device__ __forceinline__ uint32_t pkb(bf16 a, bf16 b) {
    return (uint32_t)__bfloat16_as_ushort(a) | ((uint32_t)__bfloat16_as_ushort(b) << 16);
}

// rowwise split of fp32 array into 2 bf16 planes (same layout)
__global__ __launch_bounds__(256) void split2_kernel(
    const float4* __restrict__ src, uint2* __restrict__ p0, uint2* __restrict__ p1)
{
    long i = (long)blockIdx.x * 256 + threadIdx.x;
    float4 x = src[i];
    bf16 h0, l0, h1, l1, h2, l2, h3, l3;
    split2f(x.x, h0, l0);
    split2f(x.y, h1, l1);
    split2f(x.z, h2, l2);
    split2f(x.w, h3, l3);
    p0[i] = make_uint2(pkb(h0, h1), pkb(h2, h3));
    p1[i] = make_uint2(pkb(l0, l1), pkb(l2, l3));
}

// transpose + split: W [K][N] fp32 -> 2 planes [N][K] bf16
__global__ __launch_bounds__(256) void convw2_kernel(
    const float* __restrict__ w, bf16* __restrict__ q0, bf16* __restrict__ q1,
    int K, int N)
{
    __shared__ float s[32][36];
    int n0 = blockIdx.x * 32, k0 = blockIdx.y * 32;
    int r = threadIdx.x >> 3, c4 = (threadIdx.x & 7) * 4;
    *(float4*)&s[r][c4] = *(const float4*)(w + (long)(k0 + r) * N + n0 + c4);
    __syncthreads();
#pragma unroll
    for (int j = 0; j < 4; j++) {
        float x = s[c4 + j][r];
        bf16 h, l;
        split2f(x, h, l);
        long o = (long)(n0 + r) * K + k0 + c4 + j;
        q0[o] = h;
        q1[o] = l;
    }
}

// ---------------- fp32 FFMA GEMM (selector path; exact — protects top-k) ----------------
__global__ __launch_bounds__(256, 2) void gemm_kernel(
    int asel, int dsel, int do_relu,
    const float* __restrict__ Aext, int lda,
    const float* __restrict__ W, int ldw,
    const float* __restrict__ bias,
    int ldc, int K)
{
    __shared__ float As[16][132];
    __shared__ float Ws[16][128];

    int m0 = blockIdx.y * 128;
    int n0 = blockIdx.x * 128;
    int tid = threadIdx.x;
    const float* A0 = asel ? g_hid : Aext;

    int ra = tid >> 2;
    int kq = (tid & 3) * 4;
    const float* baseP[2];
#pragma unroll
    for (int i = 0; i < 2; i++)
        baseP[i] = A0 + (long)(m0 + ra + i * 64) * lda;

    int wk = tid >> 5;
    int wn = (tid & 31) * 4;

    float acc[8][8];
#pragma unroll
    for (int i = 0; i < 8; i++)
#pragma unroll
        for (int j = 0; j < 8; j++) acc[i][j] = 0.f;

    int tx = tid & 15, ty = tid >> 4;

    for (int k0 = 0; k0 < K; k0 += 16) {
#pragma unroll
        for (int i = 0; i < 2; i++) {
            float4 v = *(const float4*)(baseP[i] + k0 + kq);
            int m = ra + i * 64;
            As[kq + 0][m] = v.x; As[kq + 1][m] = v.y;
            As[kq + 2][m] = v.z; As[kq + 3][m] = v.w;
        }
#pragma unroll
        for (int i = 0; i < 2; i++) {
            int k = wk + i * 8;
            float4 v = *(const float4*)(W + (long)(k0 + k) * ldw + n0 + wn);
            *(float4*)&Ws[k][wn] = v;
        }
        __syncthreads();
#pragma unroll
        for (int kk = 0; kk < 16; kk++) {
            float a[8], b[8];
            *(float4*)(a)     = *(const float4*)&As[kk][ty * 8];
            *(float4*)(a + 4) = *(const float4*)&As[kk][ty * 8 + 4];
            *(float4*)(b)     = *(const float4*)&Ws[kk][tx * 8];
            *(float4*)(b + 4) = *(const float4*)&Ws[kk][tx * 8 + 4];
#pragma unroll
            for (int i = 0; i < 8; i++)
#pragma unroll
                for (int j = 0; j < 8; j++)
                    acc[i][j] = fmaf(a[i], b[j], acc[i][j]);
        }
        __syncthreads();
    }

    float* Cbase = (dsel == 0) ? g_hid : g_logits;
#pragma unroll
    for (int i = 0; i < 8; i++) {
        long row = m0 + ty * 8 + i;
        float* cp = Cbase + row * ldc + n0 + tx * 8;
#pragma unroll
        for (int jj = 0; jj < 8; jj += 4) {
            float4 v;
            v.x = acc[i][jj + 0] + bias[n0 + tx * 8 + jj + 0];
            v.y = acc[i][jj + 1] + bias[n0 + tx * 8 + jj + 1];
            v.z = acc[i][jj + 2] + bias[n0 + tx * 8 + jj + 2];
            v.w = acc[i][jj + 3] + bias[n0 + tx * 8 + jj + 3];
            if (do_relu) {
                v.x = fmaxf(v.x, 0.f); v.y = fmaxf(v.y, 0.f);
                v.z = fmaxf(v.z, 0.f); v.w = fmaxf(v.w, 0.f);
            }
            *(float4*)(cp + jj) = v;
        }
    }
}

// ---------------- plane-input bf16 3-pass GEMM (pg/ri path) ----------------
// BM=64, BN=128, BK=32, 256 thr (8 warps, 2m x 4n, warp tile 32x32), cp.async double buffer.
// Inputs are pre-split bf16 planes. Passes: A0*W0 + A0*W1 + A1*W0.
// mode: 0 direct rows; 1 gather token + concat emb planes; 2 gather + concat tr planes
// outmode: 0 bf16 hi/lo planes; 2 fp32 scatter via g_active
#define ROWB    80
#define APL_B   (64 * ROWB)      // 5120 bytes (A plane incl. pad)
#define WPL_B   (128 * ROWB)     // 10240
#define STAGE_B (2 * APL_B + 2 * WPL_B)   // 30720
#define MMA3_SMEM (2 * STAGE_B)           // 61440
#define OFF_A0  0
#define OFF_A1  APL_B
#define OFF_W0  (2 * APL_B)
#define OFF_W1  (2 * APL_B + WPL_B)

__device__ __forceinline__ void mma16816(float* c, const uint32_t* a, const uint32_t* b) {
    asm volatile(
        "mma.sync.aligned.m16n8k16.row.col.f32.bf16.bf16.f32 "
        "{%0,%1,%2,%3}, {%4,%5,%6,%7}, {%8,%9}, {%0,%1,%2,%3};\n"
        : "+f"(c[0]), "+f"(c[1]), "+f"(c[2]), "+f"(c[3])
        : "r"(a[0]), "r"(a[1]), "r"(a[2]), "r"(a[3]), "r"(b[0]), "r"(b[1]));
}

__global__ __launch_bounds__(256) void mma3_kernel(
    int mode, int outmode, int do_relu,
    const bf16* __restrict__ a0, const bf16* __restrict__ a1, int lda,
    const bf16* __restrict__ s0, const bf16* __restrict__ s1, int slda, int splitK,
    const bf16* __restrict__ w0, const bf16* __restrict__ w1,
    const float* __restrict__ bias,
    bf16* __restrict__ o0, bf16* __restrict__ o1,
    float* __restrict__ of, int ldc, int K)
{
    extern __shared__ __align__(16) char smem[];
    int Meff = g_count[0];
    int m0 = blockIdx.y * 64;
    if (m0 >= Meff) return;
    int n0 = blockIdx.x * 128;
    int tid = threadIdx.x;
    int wid = tid >> 5, lane = tid & 31;
    int wm = wid & 1, wn = wid >> 1;
    int g = lane >> 2, j2 = lane & 3;

    // loader mappings (all scalar state; no arrays, no lambdas)
    int arow = tid >> 2;              // 0..63
    int aoff = (tid & 3) * 8;         // bf16 elems within 32-chunk
    uint32_t adst = (uint32_t)(arow * ROWB + (tid & 3) * 16);
    uint32_t wdstA = (uint32_t)(arow * ROWB + (tid & 3) * 16);
    uint32_t wdstB = wdstA + (uint32_t)(64 * ROWB);

    const bf16* aprim0;
    const bf16* aprim1;
    const bf16* asec0;
    const bf16* asec1;
    {
        int rg = m0 + arow;
        if (mode == 0) {
            aprim0 = a0 + (long)rg * lda;  asec0 = aprim0;
            aprim1 = a1 + (long)rg * lda;  asec1 = aprim1;
        } else {
            int rr  = (rg < Meff) ? rg : (Meff - 1);
            int tok = g_active[rr];
            int srow = (mode == 1) ? g_tool[rr] : rr;
            aprim0 = a0 + (long)tok * lda;
            aprim1 = a1 + (long)tok * lda;
            asec0  = s0 + (long)srow * slda;
            asec1  = s1 + (long)srow * slda;
        }
    }
    const bf16* wp0a = w0 + (long)(n0 + arow) * K + aoff;
    const bf16* wp0b = w0 + (long)(n0 + arow + 64) * K + aoff;
    const bf16* wp1a = w1 + (long)(n0 + arow) * K + aoff;
    const bf16* wp1b = w1 + (long)(n0 + arow + 64) * K + aoff;

    uint32_t sb = smem_u32(smem);
    int S = K / 32;

#define MMA3_ISSUE(s_) do { \
    uint32_t bp_ = sb + (uint32_t)(((s_) & 1) * STAGE_B); \
    int k0_ = (s_) * 32; \
    const bf16* sa0_ = (k0_ < splitK) ? (aprim0 + k0_ + aoff) : (asec0 + (k0_ - splitK) + aoff); \
    cp16(bp_ + OFF_A0 + adst, sa0_); \
    const bf16* sa1_ = (k0_ < splitK) ? (aprim1 + k0_ + aoff) : (asec1 + (k0_ - splitK) + aoff); \
    cp16(bp_ + OFF_A1 + adst, sa1_); \
    cp16(bp_ + OFF_W0 + wdstA, wp0a + k0_); \
    cp16(bp_ + OFF_W0 + wdstB, wp0b + k0_); \
    cp16(bp_ + OFF_W1 + wdstA, wp1a + k0_); \
    cp16(bp_ + OFF_W1 + wdstB, wp1b + k0_); \
    cp_commit(); \
} while (0)

    float acc[2][4][4];
#pragma unroll
    for (int i = 0; i < 2; i++)
#pragma unroll
        for (int j = 0; j < 4; j++)
#pragma unroll
            for (int q = 0; q < 4; q++) acc[i][j][q] = 0.f;

    MMA3_ISSUE(0);
    for (int s = 0; s < S; s++) {
        if (s + 1 < S) { MMA3_ISSUE(s + 1); cp_wait1(); }
        else           { cp_wait0(); }
        __syncthreads();
        {
            const char* bp = smem + (s & 1) * STAGE_B;
#pragma unroll
            for (int ks = 0; ks < 2; ks++) {
                int kk = ks * 16 + j2 * 2;
                uint32_t af0[2][4], af1[2][4];
#pragma unroll
                for (int mi = 0; mi < 2; mi++) {
                    int row = wm * 32 + mi * 16 + g;
                    int b0 = row * ROWB + kk * 2;
                    af0[mi][0] = *(const uint32_t*)(bp + OFF_A0 + b0);
                    af0[mi][1] = *(const uint32_t*)(bp + OFF_A0 + b0 + 8 * ROWB);
                    af0[mi][2] = *(const uint32_t*)(bp + OFF_A0 + b0 + 16);
                    af0[mi][3] = *(const uint32_t*)(bp + OFF_A0 + b0 + 8 * ROWB + 16);
                    af1[mi][0] = *(const uint32_t*)(bp + OFF_A1 + b0);
                    af1[mi][1] = *(const uint32_t*)(bp + OFF_A1 + b0 + 8 * ROWB);
                    af1[mi][2] = *(const uint32_t*)(bp + OFF_A1 + b0 + 16);
                    af1[mi][3] = *(const uint32_t*)(bp + OFF_A1 + b0 + 8 * ROWB + 16);
                }
#pragma unroll
                for (int nf = 0; nf < 4; nf++) {
                    int n = wn * 32 + nf * 8 + g;
                    int o = n * ROWB + kk * 2;
                    uint32_t wf0[2], wf1[2];
                    wf0[0] = *(const uint32_t*)(bp + OFF_W0 + o);
                    wf0[1] = *(const uint32_t*)(bp + OFF_W0 + o + 16);
                    wf1[0] = *(const uint32_t*)(bp + OFF_W1 + o);
                    wf1[1] = *(const uint32_t*)(bp + OFF_W1 + o + 16);
#pragma unroll
                    for (int mi = 0; mi < 2; mi++) {
                        mma16816(acc[mi][nf], af0[mi], wf0);
                        mma16816(acc[mi][nf], af0[mi], wf1);
                        mma16816(acc[mi][nf], af1[mi], wf0);
                    }
                }
            }
        }
        __syncthreads();
    }

    // ---- epilogue ----
#pragma unroll
    for (int mi = 0; mi < 2; mi++) {
#pragma unroll
        for (int h = 0; h < 2; h++) {
            int m = m0 + wm * 32 + mi * 16 + g + 8 * h;
            if (outmode == 2 && m >= Meff) continue;
            long orow = (outmode == 2) ? (long)g_active[m] : (long)m;
#pragma unroll
            for (int nf = 0; nf < 4; nf++) {
                int nn = n0 + wn * 32 + nf * 8 + j2 * 2;
                float vx = acc[mi][nf][h * 2 + 0] + bias[nn];
                float vy = acc[mi][nf][h * 2 + 1] + bias[nn + 1];
                if (do_relu) { vx = fmaxf(vx, 0.f); vy = fmaxf(vy, 0.f); }
                if (outmode == 2) {
                    *(float2*)(of + orow * ldc + nn) = make_float2(vx, vy);
                } else {
                    bf16 hx, lx, hy, ly;
                    split2f(vx, hx, lx);
                    split2f(vy, hy, ly);
                    long o = orow * ldc + nn;
                    *(uint32_t*)(o0 + o) = pkb(hx, hy);
                    *(uint32_t*)(o1 + o) = pkb(lx, ly);
                }
            }
        }
    }
#undef MMA3_ISSUE
}

// ---------------- launch ----------------
extern "C" void kernel_launch(void* const* d_in, const int* in_sizes, int n_in,
                              void* d_out, int out_size)
{
    const float* hidden = (const float*)d_in[0];
    const float* emb    = (const float*)d_in[1];
    const float* gate_w = (const float*)d_in[2];
    const float* gate_b = (const float*)d_in[3];
    const float* sel_w1 = (const float*)d_in[4];
    const float* sel_b1 = (const float*)d_in[5];
    const float* sel_w2 = (const float*)d_in[6];
    const float* sel_b2 = (const float*)d_in[7];
    const float* pg_w1  = (const float*)d_in[8];
    const float* pg_b1  = (const float*)d_in[9];
    const float* pg_w2  = (const float*)d_in[10];
    const float* pg_b2  = (const float*)d_in[11];
    const float* ri_w1  = (const float*)d_in[12];
    const float* ri_b1  = (const float*)d_in[13];
    const float* ri_w2  = (const float*)d_in[14];
    const float* ri_b2  = (const float*)d_in[15];

    float* out        = (float*)d_out;
    float* out_enh    = out;
    float* out_probs  = ((long)out_size >= (long)NT * (H + T))     ? out + (long)NT * H       : nullptr;
    float* out_should = ((long)out_size >= (long)NT * (H + T + 1)) ? out + (long)NT * (H + T) : nullptr;

    cudaFuncSetAttribute(mma3_kernel, cudaFuncAttributeMaxDynamicSharedMemorySize, MMA3_SMEM);

    void *p_gh, *p_hp, *p_tr, *p_eb, *p_pw1t, *p_pw2t, *p_rw1t, *p_rw2t;
    cudaGetSymbolAddress(&p_gh, g_gh);
    cudaGetSymbolAddress(&p_hp, g_hp);
    cudaGetSymbolAddress(&p_tr, g_tr);
    cudaGetSymbolAddress(&p_eb, g_eb);
    cudaGetSymbolAddress(&p_pw1t, g_pw1t);
    cudaGetSymbolAddress(&p_pw2t, g_pw2t);
    cudaGetSymbolAddress(&p_rw1t, g_rw1t);
    cudaGetSymbolAddress(&p_rw2t, g_rw2t);

    const long GH_P = (long)NT * H;
    const long HS_P = (long)NT * THID;
    bf16* gh0 = (bf16*)p_gh;     bf16* gh1 = gh0 + GH_P;
    bf16* hp0 = (bf16*)p_hp;     bf16* hp1 = hp0 + HS_P;
    bf16* tr0 = (bf16*)p_tr;     bf16* tr1 = tr0 + GH_P;
    bf16* eb0 = (bf16*)p_eb;     bf16* eb1 = eb0 + (long)T * E;
    bf16* pw1t0 = (bf16*)p_pw1t; bf16* pw1t1 = pw1t0 + (long)THID * (H + E);
    bf16* pw2t0 = (bf16*)p_pw2t; bf16* pw2t1 = pw2t0 + (long)H * THID;
    bf16* rw1t0 = (bf16*)p_rw1t; bf16* rw1t1 = rw1t0 + (long)THID * 2 * H;
    bf16* rw2t0 = (bf16*)p_rw2t; bf16* rw2t1 = rw2t0 + (long)H * THID;

    // 0) counter
    init_kernel<<<1, 1>>>();

    // 1) enhanced = hidden (default) + exact fp32 gate
    copy_gate_kernel<<<NT, 256>>>(hidden, gate_w, out_enh);

    // 2) conversions (planes for the value path)
    split2_kernel<<<(int)(GH_P / 4 / 256), 256>>>((const float4*)hidden, (uint2*)gh0, (uint2*)gh1);
    split2_kernel<<<(T * E / 4) / 256, 256>>>((const float4*)emb, (uint2*)eb0, (uint2*)eb1);
    convw2_kernel<<<dim3(THID / 32, (H + E) / 32), 256>>>(pg_w1, pw1t0, pw1t1, H + E, THID);
    convw2_kernel<<<dim3(H / 32, THID / 32), 256>>>(pg_w2, pw2t0, pw2t1, THID, H);
    convw2_kernel<<<dim3(THID / 32, 2 * H / 32), 256>>>(ri_w1, rw1t0, rw1t1, 2 * H, THID);
    convw2_kernel<<<dim3(H / 32, THID / 32), 256>>>(ri_w2, rw2t0, rw2t1, THID, H);

    // 3) sel1 (fp32 exact): h1 = relu(hidden @ sel_w1 + b1) -> g_hid [NT,512]
    gemm_kernel<<<dim3(THID / 128, NT / 128), 256>>>(
        0, 0, 1, hidden, H, sel_w1, THID, sel_b1, THID, H);

    // 4) sel2 (fp32 exact): logits -> g_logits [NT,128]
    gemm_kernel<<<dim3(T / 128, NT / 128), 256>>>(
        1, 3, 0, nullptr, THID, sel_w2, T, sel_b2, T, THID);

    // 5) top-3 + gate + compaction
    topk_kernel<<<NT / 8, 256>>>(gate_b, out_probs, out_should);

    // 6) pg1: relu(concat(h, emb[tool]) @ pg_w1 + b1) -> hp planes (compact rows)
    mma3_kernel<<<dim3(THID / 128, NT / 64), 256, MMA3_SMEM>>>(
        1, 0, 1,
        gh0, gh1, H, eb0, eb1, E, H,
        pw1t0, pw1t1, pg_b1,
        hp0, hp1, nullptr, THID, H + E);

    // 7) pg2: tool_result -> tr planes
    mma3_kernel<<<dim3(H / 128, NT / 64), 256, MMA3_SMEM>>>(
        0, 0, 0,
        hp0, hp1, THID, nullptr, nullptr, 0, THID,
        pw2t0, pw2t1, pg_b2,
        tr0, tr1, nullptr, H, THID);

    // 8) ri1: relu(concat(h, tool_result) @ ri_w1 + b1) -> hp planes (reused)
    mma3_kernel<<<dim3(THID / 128, NT / 64), 256, MMA3_SMEM>>>(
        2, 0, 1,
        gh0, gh1, H, tr0, tr1, H, H,
        rw1t0, rw1t1, ri_b1,
        hp0, hp1, nullptr, THID, 2 * H);

    // 9) ri2: integrated -> fp32 scatter into enhanced
    mma3_kernel<<<dim3(H / 128, NT / 64), 256, MMA3_SMEM>>>(
        0, 2, 0,
        hp0, hp1, THID, nullptr, nullptr, 0, THID,
        rw2t0, rw2t1, ri_b2,
        nullptr, nullptr, out_enh, H, THID);
}

// round 9
// speedup vs baseline: 1.1273x; 1.0187x over previous
#include <cuda_runtime.h>
#include <cuda_bf16.h>
#include <math.h>
#include <stdint.h>

// ---------------- problem constants ----------------
#define NT   16384      // B*S tokens
#define H    2048
#define E    256
#define THID 512
#define T    128
#define NREG 64

typedef __nv_bfloat16 bf16;

// ---------------- scratch (device globals) ----------------
__device__ float g_hid[(long)NT * THID];          // sel h1 (fp32, selector path)
__device__ uint4 g_gh[2][(long)NT * H / 8];       // hidden bf16 planes (hi, lo)
__device__ uint4 g_hp[2][(long)NT * THID / 8];    // pg-h1 planes; reused for ri-h1
__device__ uint4 g_tr[2][(long)NT * H / 8];       // tool_result planes
__device__ uint4 g_eb[2][T * E / 8];              // emb planes
__device__ uint4 g_pw1t[2][THID * (H + E) / 8];   // pg_w1^T planes [N][K]
__device__ uint4 g_pw2t[2][H * THID / 8];
__device__ uint4 g_rw1t[2][THID * 2 * H / 8];
__device__ uint4 g_rw2t[2][H * THID / 8];

__device__ float g_logits[(long)NT * T];
__device__ float g_gate[NT];
__device__ int   g_active[NT];
__device__ int   g_tool[NT];
__device__ int   g_count[1];

// ---------------- ptx helpers ----------------
__device__ __forceinline__ uint32_t smem_u32(const void* p) {
    uint32_t a;
    asm("{ .reg .u64 tmp; cvta.to.shared.u64 tmp, %1; cvt.u32.u64 %0, tmp; }"
        : "=r"(a) : "l"(p));
    return a;
}
__device__ __forceinline__ void cp16(uint32_t dst, const void* src) {
    asm volatile("cp.async.ca.shared.global [%0], [%1], 16;" :: "r"(dst), "l"(src));
}
__device__ __forceinline__ void cp_commit() { asm volatile("cp.async.commit_group;" ::: "memory"); }
__device__ __forceinline__ void cp_wait0()  { asm volatile("cp.async.wait_group 0;" ::: "memory"); }
__device__ __forceinline__ void cp_wait1()  { asm volatile("cp.async.wait_group 1;" ::: "memory"); }

// ---------------- split helpers ----------------
__device__ __forceinline__ void split2f(float x, bf16& h, bf16& l) {
    h = __float2bfloat16(x);
    l = __float2bfloat16(x - __bfloat162float(h));
}
__device__ __forceinline__ uint32_t pkb(bf16 a, bf16 b) {
    return (uint32_t)__bfloat16_as_ushort(a) | ((uint32_t)__bfloat16_as_ushort(b) << 16);
}

// ---------------- tiny kernels ----------------
__global__ void init_kernel() { g_count[0] = 0; }

// copy hidden -> out, exact fp32 gate dot, AND emit hidden hi/lo bf16 planes.
// One pass over hidden serves: default output, gate, and the mma value path.
__global__ __launch_bounds__(256) void copy_gate_split_kernel(
    const float* __restrict__ src, const float* __restrict__ gw,
    float* __restrict__ dst, uint4* __restrict__ p0, uint4* __restrict__ p1)
{
    __shared__ float red[8];
    int t = blockIdx.x, tid = threadIdx.x;
    long base = (long)t * H + tid * 8;
    float4 a = *(const float4*)(src + base);
    float4 b = *(const float4*)(src + base + 4);
    *(float4*)(dst + base)     = a;
    *(float4*)(dst + base + 4) = b;

    bf16 h0,l0,h1,l1,h2,l2,h3,l3,h4,l4,h5,l5,h6,l6,h7,l7;
    split2f(a.x,h0,l0); split2f(a.y,h1,l1); split2f(a.z,h2,l2); split2f(a.w,h3,l3);
    split2f(b.x,h4,l4); split2f(b.y,h5,l5); split2f(b.z,h6,l6); split2f(b.w,h7,l7);
    long pi = (long)t * (H / 8) + tid;
    p0[pi] = make_uint4(pkb(h0,h1), pkb(h2,h3), pkb(h4,h5), pkb(h6,h7));
    p1[pi] = make_uint4(pkb(l0,l1), pkb(l2,l3), pkb(l4,l5), pkb(l6,l7));

    float4 w0 = *(const float4*)(gw + tid * 8);
    float4 w1 = *(const float4*)(gw + tid * 8 + 4);
    float acc = a.x*w0.x + a.y*w0.y + a.z*w0.z + a.w*w0.w
              + b.x*w1.x + b.y*w1.y + b.z*w1.z + b.w*w1.w;
#pragma unroll
    for (int off = 16; off >= 1; off >>= 1)
        acc += __shfl_xor_sync(0xffffffffu, acc, off);
    if ((tid & 31) == 0) red[tid >> 5] = acc;
    __syncthreads();
    if (tid == 0) {
        float s = 0.f;
#pragma unroll
        for (int i = 0; i < 8; i++) s += red[i];
        g_gate[t] = s;
    }
}

__global__ __launch_bounds__(256) void topk_kernel(
    const float* __restrict__ gate_b,
    float* __restrict__ out_probs, float* __restrict__ out_should)
{
    int t = blockIdx.x * 8 + (threadIdx.x >> 5);
    int l = threadIdx.x & 31;
    float4 v = *(const float4*)(g_logits + (long)t * T + l * 4);
    float lg[4] = {v.x, v.y, v.z, v.w};
    int topi[3];
    unsigned mask = 0;
    float mx = 0.f;
#pragma unroll
    for (int r = 0; r < 3; r++) {
        float bv = -3.4e38f; int bi = 1 << 30;
#pragma unroll
        for (int j = 0; j < 4; j++) {
            if (!((mask >> j) & 1)) {
                int c = l * 4 + j;
                if (lg[j] > bv || (lg[j] == bv && c < bi)) { bv = lg[j]; bi = c; }
            }
        }
#pragma unroll
        for (int off = 16; off >= 1; off >>= 1) {
            float ov = __shfl_xor_sync(0xffffffffu, bv, off);
            int   oi = __shfl_xor_sync(0xffffffffu, bi, off);
            if (ov > bv || (ov == bv && oi < bi)) { bv = ov; bi = oi; }
        }
        if (r == 0) mx = bv;
        topi[r] = bi;
        if ((bi >> 2) == l) mask |= 1u << (bi & 3);
    }
    float e[4], s = 0.f;
#pragma unroll
    for (int j = 0; j < 4; j++) { e[j] = expf(lg[j] - mx); s += e[j]; }
#pragma unroll
    for (int off = 16; off >= 1; off >>= 1)
        s += __shfl_xor_sync(0xffffffffu, s, off);
    if (out_probs)
        *(float4*)(out_probs + (long)t * T + l * 4) = make_float4(e[0]/s, e[1]/s, e[2]/s, e[3]/s);
    if (l == 0) {
        bool should = (g_gate[t] + gate_b[0]) > 0.f;
        if (out_should) out_should[t] = should ? 1.0f : 0.0f;
        int last = -1, tool = 0;
#pragma unroll
        for (int k = 0; k < 3; k++)
            if (should && topi[k] < NREG) { last = k; tool = topi[k]; }
        if (last >= 0) {
            int pos = atomicAdd(g_count, 1);
            g_active[pos] = t;
            g_tool[pos]   = tool;
        }
    }
}

// rowwise split of fp32 array into 2 bf16 planes (same layout) — emb only now
__global__ __launch_bounds__(256) void split2_kernel(
    const float4* __restrict__ src, uint2* __restrict__ p0, uint2* __restrict__ p1)
{
    long i = (long)blockIdx.x * 256 + threadIdx.x;
    float4 x = src[i];
    bf16 h0, l0, h1, l1, h2, l2, h3, l3;
    split2f(x.x, h0, l0);
    split2f(x.y, h1, l1);
    split2f(x.z, h2, l2);
    split2f(x.w, h3, l3);
    p0[i] = make_uint2(pkb(h0, h1), pkb(h2, h3));
    p1[i] = make_uint2(pkb(l0, l1), pkb(l2, l3));
}

// transpose + split: W [K][N] fp32 -> 2 planes [N][K] bf16
__global__ __launch_bounds__(256) void convw2_kernel(
    const float* __restrict__ w, bf16* __restrict__ q0, bf16* __restrict__ q1,
    int K, int N)
{
    __shared__ float s[32][36];
    int n0 = blockIdx.x * 32, k0 = blockIdx.y * 32;
    int r = threadIdx.x >> 3, c4 = (threadIdx.x & 7) * 4;
    *(float4*)&s[r][c4] = *(const float4*)(w + (long)(k0 + r) * N + n0 + c4);
    __syncthreads();
#pragma unroll
    for (int j = 0; j < 4; j++) {
        float x = s[c4 + j][r];
        bf16 h, l;
        split2f(x, h, l);
        long o = (long)(n0 + r) * K + k0 + c4 + j;
        q0[o] = h;
        q1[o] = l;
    }
}

// ---------------- fp32 FFMA GEMM v2 (selector path; exact — protects top-k) ----------------
// BM=128, BN=64, BK=16, 256 thr, 8x4 thread tile (acc=32) -> ~70 regs -> 3 CTAs/SM.
// asel: 0 A=Aext, 1 A=g_hid.   dsel: 0 -> g_hid, else -> g_logits
__global__ __launch_bounds__(256, 3) void gemm2_kernel(
    int asel, int dsel, int do_relu,
    const float* __restrict__ Aext, int lda,
    const float* __restrict__ W, int ldw,    // [K, N] row-major
    const float* __restrict__ bias,
    int ldc, int K)
{
    __shared__ float As[16][132];
    __shared__ float Ws[16][68];

    int m0 = blockIdx.y * 128;
    int n0 = blockIdx.x * 64;
    int tid = threadIdx.x;
    const float* A0 = asel ? g_hid : Aext;

    int ar = tid >> 1, ak = (tid & 1) * 8;
    const float* arow = A0 + (long)(m0 + ar) * lda + ak;
    int br = tid >> 4, bc = (tid & 15) * 4;
    const float* brow = W + (long)br * ldw + n0 + bc;

    int tx = tid & 15, ty = tid >> 4;

    float acc[8][4];
#pragma unroll
    for (int i = 0; i < 8; i++)
#pragma unroll
        for (int j = 0; j < 4; j++) acc[i][j] = 0.f;

    for (int k0 = 0; k0 < K; k0 += 16) {
        float4 a0 = *(const float4*)(arow + k0);
        float4 a1 = *(const float4*)(arow + k0 + 4);
        float4 bv = *(const float4*)(brow + (long)k0 * ldw);
        As[ak + 0][ar] = a0.x; As[ak + 1][ar] = a0.y;
        As[ak + 2][ar] = a0.z; As[ak + 3][ar] = a0.w;
        As[ak + 4][ar] = a1.x; As[ak + 5][ar] = a1.y;
        As[ak + 6][ar] = a1.z; As[ak + 7][ar] = a1.w;
        *(float4*)&Ws[br][bc] = bv;
        __syncthreads();
#pragma unroll
        for (int kk = 0; kk < 16; kk++) {
            float a[8], b[4];
            *(float4*)(a)     = *(const float4*)&As[kk][ty * 8];
            *(float4*)(a + 4) = *(const float4*)&As[kk][ty * 8 + 4];
            *(float4*)(b)     = *(const float4*)&Ws[kk][tx * 4];
#pragma unroll
            for (int i = 0; i < 8; i++)
#pragma unroll
                for (int j = 0; j < 4; j++)
                    acc[i][j] = fmaf(a[i], b[j], acc[i][j]);
        }
        __syncthreads();
    }

    float* Cbase = (dsel == 0) ? g_hid : g_logits;
#pragma unroll
    for (int i = 0; i < 8; i++) {
        long row = m0 + ty * 8 + i;
        float* cp = Cbase + row * ldc + n0 + tx * 4;
        float4 v;
        v.x = acc[i][0] + bias[n0 + tx * 4 + 0];
        v.y = acc[i][1] + bias[n0 + tx * 4 + 1];
        v.z = acc[i][2] + bias[n0 + tx * 4 + 2];
        v.w = acc[i][3] + bias[n0 + tx * 4 + 3];
        if (do_relu) {
            v.x = fmaxf(v.x, 0.f); v.y = fmaxf(v.y, 0.f);
            v.z = fmaxf(v.z, 0.f); v.w = fmaxf(v.w, 0.f);
        }
        *(float4*)cp = v;
    }
}

// ---------------- plane-input bf16 3-pass GEMM (pg/ri path) — unchanged from R8 ----------------
#define ROWB    80
#define APL_B   (64 * ROWB)
#define WPL_B   (128 * ROWB)
#define STAGE_B (2 * APL_B + 2 * WPL_B)
#define MMA3_SMEM (2 * STAGE_B)
#define OFF_A0  0
#define OFF_A1  APL_B
#define OFF_W0  (2 * APL_B)
#define OFF_W1  (2 * APL_B + WPL_B)

__device__ __forceinline__ void mma16816(float* c, const uint32_t* a, const uint32_t* b) {
    asm volatile(
        "mma.sync.aligned.m16n8k16.row.col.f32.bf16.bf16.f32 "
        "{%0,%1,%2,%3}, {%4,%5,%6,%7}, {%8,%9}, {%0,%1,%2,%3};\n"
        : "+f"(c[0]), "+f"(c[1]), "+f"(c[2]), "+f"(c[3])
        : "r"(a[0]), "r"(a[1]), "r"(a[2]), "r"(a[3]), "r"(b[0]), "r"(b[1]));
}

__global__ __launch_bounds__(256) void mma3_kernel(
    int mode, int outmode, int do_relu,
    const bf16* __restrict__ a0, const bf16* __restrict__ a1, int lda,
    const bf16* __restrict__ s0, const bf16* __restrict__ s1, int slda, int splitK,
    const bf16* __restrict__ w0, const bf16* __restrict__ w1,
    const float* __restrict__ bias,
    bf16* __restrict__ o0, bf16* __restrict__ o1,
    float* __restrict__ of, int ldc, int K)
{
    extern __shared__ __align__(16) char smem[];
    int Meff = g_count[0];
    int m0 = blockIdx.y * 64;
    if (m0 >= Meff) return;
    int n0 = blockIdx.x * 128;
    int tid = threadIdx.x;
    int wid = tid >> 5, lane = tid & 31;
    int wm = wid & 1, wn = wid >> 1;
    int g = lane >> 2, j2 = lane & 3;

    int arow = tid >> 2;
    int aoff = (tid & 3) * 8;
    uint32_t adst = (uint32_t)(arow * ROWB + (tid & 3) * 16);
    uint32_t wdstA = adst;
    uint32_t wdstB = adst + (uint32_t)(64 * ROWB);

    const bf16* aprim0;
    const bf16* aprim1;
    const bf16* asec0;
    const bf16* asec1;
    {
        int rg = m0 + arow;
        if (mode == 0) {
            aprim0 = a0 + (long)rg * lda;  asec0 = aprim0;
            aprim1 = a1 + (long)rg * lda;  asec1 = aprim1;
        } else {
            int rr  = (rg < Meff) ? rg : (Meff - 1);
            int tok = g_active[rr];
            int srow = (mode == 1) ? g_tool[rr] : rr;
            aprim0 = a0 + (long)tok * lda;
            aprim1 = a1 + (long)tok * lda;
            asec0  = s0 + (long)srow * slda;
            asec1  = s1 + (long)srow * slda;
        }
    }
    const bf16* wp0a = w0 + (long)(n0 + arow) * K + aoff;
    const bf16* wp0b = w0 + (long)(n0 + arow + 64) * K + aoff;
    const bf16* wp1a = w1 + (long)(n0 + arow) * K + aoff;
    const bf16* wp1b = w1 + (long)(n0 + arow + 64) * K + aoff;

    uint32_t sb = smem_u32(smem);
    int S = K / 32;

#define MMA3_ISSUE(s_) do { \
    uint32_t bp_ = sb + (uint32_t)(((s_) & 1) * STAGE_B); \
    int k0_ = (s_) * 32; \
    const bf16* sa0_ = (k0_ < splitK) ? (aprim0 + k0_ + aoff) : (asec0 + (k0_ - splitK) + aoff); \
    cp16(bp_ + OFF_A0 + adst, sa0_); \
    const bf16* sa1_ = (k0_ < splitK) ? (aprim1 + k0_ + aoff) : (asec1 + (k0_ - splitK) + aoff); \
    cp16(bp_ + OFF_A1 + adst, sa1_); \
    cp16(bp_ + OFF_W0 + wdstA, wp0a + k0_); \
    cp16(bp_ + OFF_W0 + wdstB, wp0b + k0_); \
    cp16(bp_ + OFF_W1 + wdstA, wp1a + k0_); \
    cp16(bp_ + OFF_W1 + wdstB, wp1b + k0_); \
    cp_commit(); \
} while (0)

    float acc[2][4][4];
#pragma unroll
    for (int i = 0; i < 2; i++)
#pragma unroll
        for (int j = 0; j < 4; j++)
#pragma unroll
            for (int q = 0; q < 4; q++) acc[i][j][q] = 0.f;

    MMA3_ISSUE(0);
    for (int s = 0; s < S; s++) {
        if (s + 1 < S) { MMA3_ISSUE(s + 1); cp_wait1(); }
        else           { cp_wait0(); }
        __syncthreads();
        {
            const char* bp = smem + (s & 1) * STAGE_B;
#pragma unroll
            for (int ks = 0; ks < 2; ks++) {
                int kk = ks * 16 + j2 * 2;
                uint32_t af0[2][4], af1[2][4];
#pragma unroll
                for (int mi = 0; mi < 2; mi++) {
                    int row = wm * 32 + mi * 16 + g;
                    int b0 = row * ROWB + kk * 2;
                    af0[mi][0] = *(const uint32_t*)(bp + OFF_A0 + b0);
                    af0[mi][1] = *(const uint32_t*)(bp + OFF_A0 + b0 + 8 * ROWB);
                    af0[mi][2] = *(const uint32_t*)(bp + OFF_A0 + b0 + 16);
                    af0[mi][3] = *(const uint32_t*)(bp + OFF_A0 + b0 + 8 * ROWB + 16);
                    af1[mi][0] = *(const uint32_t*)(bp + OFF_A1 + b0);
                    af1[mi][1] = *(const uint32_t*)(bp + OFF_A1 + b0 + 8 * ROWB);
                    af1[mi][2] = *(const uint32_t*)(bp + OFF_A1 + b0 + 16);
                    af1[mi][3] = *(const uint32_t*)(bp + OFF_A1 + b0 + 8 * ROWB + 16);
                }
#pragma unroll
                for (int nf = 0; nf < 4; nf++) {
                    int n = wn * 32 + nf * 8 + g;
                    int o = n * ROWB + kk * 2;
                    uint32_t wf0[2], wf1[2];
                    wf0[0] = *(const uint32_t*)(bp + OFF_W0 + o);
                    wf0[1] = *(const uint32_t*)(bp + OFF_W0 + o + 16);
                    wf1[0] = *(const uint32_t*)(bp + OFF_W1 + o);
                    wf1[1] = *(const uint32_t*)(bp + OFF_W1 + o + 16);
#pragma unroll
                    for (int mi = 0; mi < 2; mi++) {
                        mma16816(acc[mi][nf], af0[mi], wf0);
                        mma16816(acc[mi][nf], af0[mi], wf1);
                        mma16816(acc[mi][nf], af1[mi], wf0);
                    }
                }
            }
        }
        __syncthreads();
    }

#pragma unroll
    for (int mi = 0; mi < 2; mi++) {
#pragma unroll
        for (int h = 0; h < 2; h++) {
            int m = m0 + wm * 32 + mi * 16 + g + 8 * h;
            if (outmode == 2 && m >= Meff) continue;
            long orow = (outmode == 2) ? (long)g_active[m] : (long)m;
#pragma unroll
            for (int nf = 0; nf < 4; nf++) {
                int nn = n0 + wn * 32 + nf * 8 + j2 * 2;
                float vx = acc[mi][nf][h * 2 + 0] + bias[nn];
                float vy = acc[mi][nf][h * 2 + 1] + bias[nn + 1];
                if (do_relu) { vx = fmaxf(vx, 0.f); vy = fmaxf(vy, 0.f); }
                if (outmode == 2) {
                    *(float2*)(of + orow * ldc + nn) = make_float2(vx, vy);
                } else {
                    bf16 hx, lx, hy, ly;
                    split2f(vx, hx, lx);
                    split2f(vy, hy, ly);
                    long o = orow * ldc + nn;
                    *(uint32_t*)(o0 + o) = pkb(hx, hy);
                    *(uint32_t*)(o1 + o) = pkb(lx, ly);
                }
            }
        }
    }
#undef MMA3_ISSUE
}

// ---------------- launch ----------------
extern "C" void kernel_launch(void* const* d_in, const int* in_sizes, int n_in,
                              void* d_out, int out_size)
{
    const float* hidden = (const float*)d_in[0];
    const float* emb    = (const float*)d_in[1];
    const float* gate_w = (const float*)d_in[2];
    const float* gate_b = (const float*)d_in[3];
    const float* sel_w1 = (const float*)d_in[4];
    const float* sel_b1 = (const float*)d_in[5];
    const float* sel_w2 = (const float*)d_in[6];
    const float* sel_b2 = (const float*)d_in[7];
    const float* pg_w1  = (const float*)d_in[8];
    const float* pg_b1  = (const float*)d_in[9];
    const float* pg_w2  = (const float*)d_in[10];
    const float* pg_b2  = (const float*)d_in[11];
    const float* ri_w1  = (const float*)d_in[12];
    const float* ri_b1  = (const float*)d_in[13];
    const float* ri_w2  = (const float*)d_in[14];
    const float* ri_b2  = (const float*)d_in[15];

    float* out        = (float*)d_out;
    float* out_enh    = out;
    float* out_probs  = ((long)out_size >= (long)NT * (H + T))     ? out + (long)NT * H       : nullptr;
    float* out_should = ((long)out_size >= (long)NT * (H + T + 1)) ? out + (long)NT * (H + T) : nullptr;

    cudaFuncSetAttribute(mma3_kernel, cudaFuncAttributeMaxDynamicSharedMemorySize, MMA3_SMEM);

    void *p_gh, *p_hp, *p_tr, *p_eb, *p_pw1t, *p_pw2t, *p_rw1t, *p_rw2t;
    cudaGetSymbolAddress(&p_gh, g_gh);
    cudaGetSymbolAddress(&p_hp, g_hp);
    cudaGetSymbolAddress(&p_tr, g_tr);
    cudaGetSymbolAddress(&p_eb, g_eb);
    cudaGetSymbolAddress(&p_pw1t, g_pw1t);
    cudaGetSymbolAddress(&p_pw2t, g_pw2t);
    cudaGetSymbolAddress(&p_rw1t, g_rw1t);
    cudaGetSymbolAddress(&p_rw2t, g_rw2t);

    const long GH_P = (long)NT * H;
    const long HS_P = (long)NT * THID;
    bf16* gh0 = (bf16*)p_gh;     bf16* gh1 = gh0 + GH_P;
    bf16* hp0 = (bf16*)p_hp;     bf16* hp1 = hp0 + HS_P;
    bf16* tr0 = (bf16*)p_tr;     bf16* tr1 = tr0 + GH_P;
    bf16* eb0 = (bf16*)p_eb;     bf16* eb1 = eb0 + (long)T * E;
    bf16* pw1t0 = (bf16*)p_pw1t; bf16* pw1t1 = pw1t0 + (long)THID * (H + E);
    bf16* pw2t0 = (bf16*)p_pw2t; bf16* pw2t1 = pw2t0 + (long)H * THID;
    bf16* rw1t0 = (bf16*)p_rw1t; bf16* rw1t1 = rw1t0 + (long)THID * 2 * H;
    bf16* rw2t0 = (bf16*)p_rw2t; bf16* rw2t1 = rw2t0 + (long)H * THID;

    // 0) counter
    init_kernel<<<1, 1>>>();

    // 1) enhanced = hidden + exact fp32 gate + hidden hi/lo planes (one pass)
    copy_gate_split_kernel<<<NT, 256>>>(hidden, gate_w, out_enh,
                                        (uint4*)gh0, (uint4*)gh1);

    // 2) remaining conversions (weights + emb)
    split2_kernel<<<(T * E / 4) / 256, 256>>>((const float4*)emb, (uint2*)eb0, (uint2*)eb1);
    convw2_kernel<<<dim3(THID / 32, (H + E) / 32), 256>>>(pg_w1, pw1t0, pw1t1, H + E, THID);
    convw2_kernel<<<dim3(H / 32, THID / 32), 256>>>(pg_w2, pw2t0, pw2t1, THID, H);
    convw2_kernel<<<dim3(THID / 32, 2 * H / 32), 256>>>(ri_w1, rw1t0, rw1t1, 2 * H, THID);
    convw2_kernel<<<dim3(H / 32, THID / 32), 256>>>(ri_w2, rw2t0, rw2t1, THID, H);

    // 3) sel1 (fp32 exact, high-occupancy): h1 = relu(hidden @ sel_w1 + b1) -> g_hid
    gemm2_kernel<<<dim3(THID / 64, NT / 128), 256>>>(
        0, 0, 1, hidden, H, sel_w1, THID, sel_b1, THID, H);

    // 4) sel2 (fp32 exact): logits -> g_logits [NT,128]
    gemm2_kernel<<<dim3(T / 64, NT / 128), 256>>>(
        1, 3, 0, nullptr, THID, sel_w2, T, sel_b2, T, THID);

    // 5) top-3 + gate + compaction
    topk_kernel<<<NT / 8, 256>>>(gate_b, out_probs, out_should);

    // 6) pg1: relu(concat(h, emb[tool]) @ pg_w1 + b1) -> hp planes (compact rows)
    mma3_kernel<<<dim3(THID / 128, NT / 64), 256, MMA3_SMEM>>>(
        1, 0, 1,
        gh0, gh1, H, eb0, eb1, E, H,
        pw1t0, pw1t1, pg_b1,
        hp0, hp1, nullptr, THID, H + E);

    // 7) pg2: tool_result -> tr planes
    mma3_kernel<<<dim3(H / 128, NT / 64), 256, MMA3_SMEM>>>(
        0, 0, 0,
        hp0, hp1, THID, nullptr, nullptr, 0, THID,
        pw2t0, pw2t1, pg_b2,
        tr0, tr1, nullptr, H, THID);

    // 8) ri1: relu(concat(h, tool_result) @ ri_w1 + b1) -> hp planes (reused)
    mma3_kernel<<<dim3(THID / 128, NT / 64), 256, MMA3_SMEM>>>(
        2, 0, 1,
        gh0, gh1, H, tr0, tr1, H, H,
        rw1t0, rw1t1, ri_b1,
        hp0, hp1, nullptr, THID, 2 * H);

    // 9) ri2: integrated -> fp32 scatter into enhanced
    mma3_kernel<<<dim3(H / 128, NT / 64), 256, MMA3_SMEM>>>(
        0, 2, 0,
        hp0, hp1, THID, nullptr, nullptr, 0, THID,
        rw2t0, rw2t1, ri_b2,
        nullptr, nullptr, out_enh, H, THID);
}